// round 4
// baseline (speedup 1.0000x reference)
#include <cuda_runtime.h>

// NonMaximaSuppression3d: x (4,4,32,256,256) fp32.
// out = x where x is STRICTLY greater than all 26 neighbors (3x3x3 minus center),
// zero elsewhere (including all borders).
//
// Strategy: fused separable-max sweep.
//   max26(d,h,w) = max( P(d-1), P(d+1), rmC(h-1), rmC(h+1), x[w-1], x[w+1] )
// where rm(p,r) = 3-wide row max along w of plane p row r,
//       P(p)    = max over rows h-1..h+1 of rm(p,.)  (full 3x3 of adjacent plane).
// Center never enters max26, so (x > max26) is exactly the strict 26-comparison.
//
// Each thread: 4 consecutive w via float4, fixed d, slides a 3-row register
// window along h (ROWS rows per thread). 9 LDG + 1 STG per 4 outputs.

namespace {

constexpr int Dd = 32;
constexpr int Hh = 256;
constexpr int Ww = 256;
constexpr int PLANE = Hh * Ww;       // 65536
constexpr int ROWS = 32;             // output rows per thread

__device__ __forceinline__ float neg_inf() { return __int_as_float(0xff800000u); }
__device__ __forceinline__ float fmax3(float a, float b, float c) {
    return fmaxf(a, fmaxf(b, c));
}
__device__ __forceinline__ float4 f4max(float4 a, float4 b) {
    return make_float4(fmaxf(a.x, b.x), fmaxf(a.y, b.y),
                       fmaxf(a.z, b.z), fmaxf(a.w, b.w));
}

struct Row6 { float4 c; float l, r; };  // covers w0-1 .. w0+4

__device__ __forceinline__ Row6 load_row(const float* __restrict__ rowp, int w0, bool valid) {
    Row6 v;
    if (valid) {
        v.c = *reinterpret_cast<const float4*>(rowp + w0);
        v.l = (w0 > 0)       ? __ldg(rowp + w0 - 1) : neg_inf();
        v.r = (w0 + 4 < Ww)  ? __ldg(rowp + w0 + 4) : neg_inf();
    } else {
        const float ni = neg_inf();
        v.c = make_float4(ni, ni, ni, ni);
        v.l = ni;
        v.r = ni;
    }
    return v;
}

// 3-wide row max for the 4 output positions
__device__ __forceinline__ float4 rowmax4(const Row6& v) {
    float4 m;
    m.x = fmax3(v.l,   v.c.x, v.c.y);
    m.y = fmax3(v.c.x, v.c.y, v.c.z);
    m.z = fmax3(v.c.y, v.c.z, v.c.w);
    m.w = fmax3(v.c.z, v.c.w, v.r);
    return m;
}

// max(x[w-1], x[w+1]) for the 4 output positions (center excluded)
__device__ __forceinline__ float4 wex4(const Row6& v) {
    float4 m;
    m.x = fmaxf(v.l,   v.c.y);
    m.y = fmaxf(v.c.x, v.c.z);
    m.z = fmaxf(v.c.y, v.c.w);
    m.w = fmaxf(v.c.z, v.r);
    return m;
}

} // namespace

extern "C" __global__ void __launch_bounds__(256)
nms3d_kernel(const float* __restrict__ x, float* __restrict__ out)
{
    const int d  = blockIdx.x;                                   // 0..31
    const int w0 = threadIdx.x * 4;                              // 0..252
    const int hs = (blockIdx.y * blockDim.y + threadIdx.y) * ROWS; // 0..224
    const long slab = (long)blockIdx.z * (long)(Dd * PLANE);     // (b,ch) slab

    float* op = out + slab + (long)d * PLANE + w0;

    // Border planes d=0, d=31: pure zero fill (output is poisoned, must write).
    if (d == 0 || d == Dd - 1) {
        const float4 z = make_float4(0.f, 0.f, 0.f, 0.f);
        #pragma unroll 8
        for (int h = hs; h < hs + ROWS; ++h)
            *reinterpret_cast<float4*>(op + h * Ww) = z;
        return;
    }

    const float* pm = x + slab + (long)(d - 1) * PLANE;  // plane d-1
    const float* pc = pm + PLANE;                        // plane d
    const float* pp = pc + PLANE;                        // plane d+1

    // Sliding windows (index 0 = h-1, 1 = h; 2 filled in-loop for h+1):
    //   rmC*: row-max of the CENTER plane
    //   q*  : max(rowmax(plane d-1), rowmax(plane d+1))  -> off-plane combined
    float4 rmC0, rmC1, q0, q1;
    float4 wexC, xcC;  // w-exclusion max and raw center values at output row h

    // Warm-up: row hs-1
    {
        const int r = hs - 1;
        const bool rv = (r >= 0);
        Row6 vm = load_row(pm + r * Ww, w0, rv);
        Row6 vc = load_row(pc + r * Ww, w0, rv);
        Row6 vp = load_row(pp + r * Ww, w0, rv);
        rmC0 = rowmax4(vc);
        q0   = f4max(rowmax4(vm), rowmax4(vp));
    }
    // Warm-up: row hs
    {
        const int r = hs;
        Row6 vm = load_row(pm + r * Ww, w0, true);
        Row6 vc = load_row(pc + r * Ww, w0, true);
        Row6 vp = load_row(pp + r * Ww, w0, true);
        rmC1 = rowmax4(vc);
        q1   = f4max(rowmax4(vm), rowmax4(vp));
        wexC = wex4(vc);
        xcC  = vc.c;
    }

    const bool wv0 = (w0 != 0);        // lane j=0 is global border iff w0==0
    const bool wv3 = (w0 != Ww - 4);   // lane j=3 is global border iff w0==252

    #pragma unroll 4
    for (int h = hs; h < hs + ROWS; ++h) {
        const int  rn = h + 1;
        const bool rv = (rn < Hh);
        Row6 vm = load_row(pm + rn * Ww, w0, rv);
        Row6 vc = load_row(pc + rn * Ww, w0, rv);
        Row6 vp = load_row(pp + rn * Ww, w0, rv);

        const float4 rmC2 = rowmax4(vc);
        const float4 q2   = f4max(rowmax4(vm), rowmax4(vp));

        // Emit output row h.
        // off-plane (18) = max(q0,q1,q2); in-plane rows (6) = max(rmC0,rmC2);
        // in-row (2) = wexC.  Total = 26 neighbors, center excluded.
        const float4 m26 = f4max(f4max(q0, f4max(q1, q2)),
                                 f4max(f4max(rmC0, rmC2), wexC));

        const bool hv = (h >= 1) && (h <= Hh - 2);
        float4 o;
        o.x = (hv && wv0 && (xcC.x > m26.x)) ? xcC.x : 0.f;
        o.y = (hv &&        (xcC.y > m26.y)) ? xcC.y : 0.f;
        o.z = (hv &&        (xcC.z > m26.z)) ? xcC.z : 0.f;
        o.w = (hv && wv3 && (xcC.w > m26.w)) ? xcC.w : 0.f;
        *reinterpret_cast<float4*>(op + h * Ww) = o;

        // Slide windows.
        q0 = q1;     q1 = q2;
        rmC0 = rmC1; rmC1 = rmC2;
        wexC = wex4(vc);
        xcC  = vc.c;
    }
}

extern "C" void kernel_launch(void* const* d_in, const int* in_sizes, int n_in,
                              void* d_out, int out_size)
{
    const float* x = (const float*)d_in[0];
    float* out = (float*)d_out;
    (void)in_sizes; (void)n_in; (void)out_size;

    // block: 64 w-threads (x4 floats = full W=256) x 4 h-strips
    // grid:  32 d-planes x 2 h-chunks x 16 (b*ch) slabs = 1024 blocks
    dim3 block(64, 4, 1);
    dim3 grid(Dd, Hh / (ROWS * 4), 16);
    nms3d_kernel<<<grid, block>>>(x, out);
}

// round 5
// speedup vs baseline: 1.0917x; 1.0917x over previous
#include <cuda_runtime.h>

// NonMaximaSuppression3d: x (4,4,32,256,256) fp32.
// out = x where x strictly exceeds all 26 neighbors; zero elsewhere (borders zero).
//
// R5: shuffle-based w-halos (kills the strided scalar halo LDGs that dominated
// L1tex wavefronts) + 1-row software pipeline (hide DRAM latency) + 128-thread
// blocks for balance. Each warp covers 128 contiguous w via float4/lane.

namespace {

constexpr int Dd = 32;
constexpr int Hh = 256;
constexpr int Ww = 256;
constexpr int PLANE = Hh * Ww;
constexpr int ROWS = 32;   // output rows per thread

__device__ __forceinline__ float ninf() { return __int_as_float(0xff800000u); }
__device__ __forceinline__ float fmax3(float a, float b, float c) {
    return fmaxf(a, fmaxf(b, c));
}
__device__ __forceinline__ float4 f4max(float4 a, float4 b) {
    return make_float4(fmaxf(a.x, b.x), fmaxf(a.y, b.y),
                       fmaxf(a.z, b.z), fmaxf(a.w, b.w));
}

// One row of all 3 planes: float4 payload + one edge scalar per plane.
// The edge scalar is only meaningful in lanes 0 / 31 (mutually exclusive).
struct RowLd { float4 m, c, p; float em, ec, ep; };

__device__ __forceinline__ RowLd issue_row(const float* __restrict__ pm,
                                           const float* __restrict__ pc,
                                           const float* __restrict__ pp,
                                           int rn, int w0, bool rv, int ew)
{
    RowLd L;
    const float ni = ninf();
    L.m = L.c = L.p = make_float4(ni, ni, ni, ni);
    L.em = L.ec = L.ep = ni;
    if (rv) {
        const float* rm_ = pm + rn * Ww;
        const float* rc_ = pc + rn * Ww;
        const float* rp_ = pp + rn * Ww;
        L.m = *reinterpret_cast<const float4*>(rm_ + w0);
        L.c = *reinterpret_cast<const float4*>(rc_ + w0);
        L.p = *reinterpret_cast<const float4*>(rp_ + w0);
        if (ew >= 0) {              // only lanes 0 / 31, and not at image border
            L.em = __ldg(rm_ + ew);
            L.ec = __ldg(rc_ + ew);
            L.ep = __ldg(rp_ + ew);
        }
    }
    return L;
}

// Halo via shuffle: l = neighbor-lane's c.w, r = neighbor-lane's c.x.
// Warp-edge lanes substitute the explicitly loaded edge scalar (or -inf at border).
__device__ __forceinline__ float4 rowmax4s(float4 c, float e, int lane)
{
    float l = __shfl_up_sync(0xffffffffu, c.w, 1);
    float r = __shfl_down_sync(0xffffffffu, c.x, 1);
    if (lane == 0)  l = e;
    if (lane == 31) r = e;
    float4 m;
    m.x = fmax3(l,   c.x, c.y);
    m.y = fmax3(c.x, c.y, c.z);
    m.z = fmax3(c.y, c.z, c.w);
    m.w = fmax3(c.z, c.w, r);
    return m;
}

// Center plane: rowmax AND w-exclusion max (x[w-1], x[w+1]) with one shuffle pair.
__device__ __forceinline__ void reduceC(float4 c, float e, int lane,
                                        float4& rm, float4& wx)
{
    float l = __shfl_up_sync(0xffffffffu, c.w, 1);
    float r = __shfl_down_sync(0xffffffffu, c.x, 1);
    if (lane == 0)  l = e;
    if (lane == 31) r = e;
    rm.x = fmax3(l,   c.x, c.y);
    rm.y = fmax3(c.x, c.y, c.z);
    rm.z = fmax3(c.y, c.z, c.w);
    rm.w = fmax3(c.z, c.w, r);
    wx.x = fmaxf(l,   c.y);
    wx.y = fmaxf(c.x, c.z);
    wx.z = fmaxf(c.y, c.w);
    wx.w = fmaxf(c.z, r);
}

} // namespace

extern "C" __global__ void __launch_bounds__(128)
nms3d_kernel(const float* __restrict__ x, float* __restrict__ out)
{
    const int lane  = threadIdx.x;                 // 0..31, warp = one y-row
    const int d     = blockIdx.x >> 1;             // 0..31
    const int wside = blockIdx.x & 1;              // which 128-wide half of W
    const int w0    = (wside * 32 + lane) * 4;     // 0..252
    const int hs    = (blockIdx.y * blockDim.y + threadIdx.y) * ROWS;
    const long slab = (long)blockIdx.z * (long)(Dd * PLANE);

    float* op = out + slab + (long)d * PLANE + w0;

    // Border planes: pure zero fill (output is poisoned, must be written).
    if (d == 0 || d == Dd - 1) {
        const float4 z = make_float4(0.f, 0.f, 0.f, 0.f);
        #pragma unroll 8
        for (int h = hs; h < hs + ROWS; ++h)
            *reinterpret_cast<float4*>(op + h * Ww) = z;
        return;
    }

    const float* pm = x + slab + (long)(d - 1) * PLANE;
    const float* pc = pm + PLANE;
    const float* pp = pc + PLANE;

    // Edge scalar index for this lane (one per warp side; -1 = no load / border).
    int ew = -1;
    if (lane == 0  && w0 > 0)       ew = w0 - 1;
    if (lane == 31 && w0 + 4 < Ww)  ew = w0 + 4;

    // Sliding state:
    //   rmC0/rmC1: center-plane row maxes at h-1 / h
    //   q0/q1:     combined off-plane row maxes at h-1 / h
    //   wexC/xcC:  w-exclusion max and raw centers at output row h
    float4 rmC0, rmC1, q0, q1, wexC, xcC;

    { // warm-up: row hs-1
        const bool rv = (hs - 1 >= 0);
        RowLd L = issue_row(pm, pc, pp, hs - 1, w0, rv, ew);
        float4 wxd;
        reduceC(L.c, L.ec, lane, rmC0, wxd);
        q0 = f4max(rowmax4s(L.m, L.em, lane), rowmax4s(L.p, L.ep, lane));
    }
    { // warm-up: row hs
        RowLd L = issue_row(pm, pc, pp, hs, w0, true, ew);
        reduceC(L.c, L.ec, lane, rmC1, wexC);
        xcC = L.c;
        q1 = f4max(rowmax4s(L.m, L.em, lane), rowmax4s(L.p, L.ep, lane));
    }
    // Pipeline prime: loads for row hs+1 in flight.
    RowLd CUR = issue_row(pm, pc, pp, hs + 1, w0, (hs + 1) < Hh, ew);

    const bool wv0 = (w0 != 0);
    const bool wv3 = (w0 != Ww - 4);

    #pragma unroll 4
    for (int h = hs; h < hs + ROWS; ++h) {
        // Issue next row's loads FIRST (row h+2) — consumed next iteration.
        const int  rn2 = h + 2;
        const bool ld2 = (h + 1 < hs + ROWS) && (rn2 < Hh);
        RowLd NXT = issue_row(pm, pc, pp, rn2, w0, ld2, ew);

        // Reduce CUR = row h+1 (its loads were issued last iteration).
        float4 rmC2, wexN;
        reduceC(CUR.c, CUR.ec, lane, rmC2, wexN);
        const float4 q2  = f4max(rowmax4s(CUR.m, CUR.em, lane),
                                 rowmax4s(CUR.p, CUR.ep, lane));
        const float4 xcN = CUR.c;

        // 26-neighbor max: 18 off-plane (q0..q2) + 6 in-plane rows (rmC0, rmC2)
        // + 2 in-row (wexC). Center never included -> strict compare is exact.
        const float4 m26 = f4max(f4max(q0, f4max(q1, q2)),
                                 f4max(f4max(rmC0, rmC2), wexC));

        const bool hv = (h >= 1) && (h <= Hh - 2);
        float4 o;
        o.x = (hv && wv0 && (xcC.x > m26.x)) ? xcC.x : 0.f;
        o.y = (hv &&        (xcC.y > m26.y)) ? xcC.y : 0.f;
        o.z = (hv &&        (xcC.z > m26.z)) ? xcC.z : 0.f;
        o.w = (hv && wv3 && (xcC.w > m26.w)) ? xcC.w : 0.f;
        *reinterpret_cast<float4*>(op + h * Ww) = o;

        // Slide.
        q0 = q1;     q1 = q2;
        rmC0 = rmC1; rmC1 = rmC2;
        wexC = wexN; xcC = xcN;
        CUR = NXT;
    }
}

extern "C" void kernel_launch(void* const* d_in, const int* in_sizes, int n_in,
                              void* d_out, int out_size)
{
    const float* x = (const float*)d_in[0];
    float* out = (float*)d_out;
    (void)in_sizes; (void)n_in; (void)out_size;

    // block: 32 lanes (x4 floats = 128 w) x 4 h-strips = 128 threads
    // grid:  (32 d x 2 w-sides) x 2 h-chunks x 16 (b*ch) slabs = 2048 blocks
    dim3 block(32, 4, 1);
    dim3 grid(Dd * 2, Hh / (ROWS * 4), 16);
    nms3d_kernel<<<grid, block>>>(x, out);
}